// round 2
// baseline (speedup 1.0000x reference)
#include <cuda_runtime.h>

#define NN 50000
#define NE 800000
#define EMB 64
#define NL 4
#define BN_EPS 1e-5f

typedef unsigned long long ull;

// ---------------- device scratch (no allocations allowed) ----------------
__device__ float  g_h [NN*EMB];
__device__ float  g_u [NN*EMB];
__device__ float  g_t1[NN*EMB];
__device__ float  g_t2[NN*EMB];
__device__ int    g_deg[NN];
__device__ int    g_off[NN+1];
__device__ int    g_cur[NN];
__device__ float2 g_csr[NE];          // (src as int bits, weight)
__device__ float  g_sum[EMB];
__device__ float  g_ss [EMB];
__device__ float  g_a  [EMB];
__device__ float  g_c  [EMB];

// ---------------- small helpers: packed f32x2 FMA ----------------
__device__ __forceinline__ ull pack2(float a, float b){
    ull r; asm("mov.b64 %0, {%1, %2};" : "=l"(r) : "f"(a), "f"(b)); return r;
}
__device__ __forceinline__ float2 unpack2(ull v){
    float2 r; asm("mov.b64 {%0, %1}, %2;" : "=f"(r.x), "=f"(r.y) : "l"(v)); return r;
}
__device__ __forceinline__ void ffma2(ull &d, ull a, ull b){
    asm("fma.rn.f32x2 %0, %1, %2, %0;" : "+l"(d) : "l"(a), "l"(b));
}

// ---------------- CSR build ----------------
__global__ void k_init(){
    int i = blockIdx.x*blockDim.x + threadIdx.x;
    if (i < NN) g_deg[i] = 0;
    if (i < EMB){ g_sum[i] = 0.f; g_ss[i] = 0.f; }
}

__global__ void k_hist(const int* __restrict__ ei){
    int e = blockIdx.x*blockDim.x + threadIdx.x;
    if (e < NE) atomicAdd(&g_deg[ei[NE + e]], 1);
}

__global__ void k_scan(){
    __shared__ int wsum[32];
    __shared__ int s_carry;
    int tid = threadIdx.x, lane = tid & 31, wid = tid >> 5;
    if (tid == 0) s_carry = 0;
    __syncthreads();
    for (int base = 0; base < NN; base += 1024){
        int i = base + tid;
        int v = (i < NN) ? g_deg[i] : 0;
        int x = v;
        #pragma unroll
        for (int d = 1; d < 32; d <<= 1){
            int t = __shfl_up_sync(0xffffffffu, x, d);
            if (lane >= d) x += t;
        }
        if (lane == 31) wsum[wid] = x;
        __syncthreads();
        if (wid == 0){
            int y = wsum[lane];
            #pragma unroll
            for (int d = 1; d < 32; d <<= 1){
                int t = __shfl_up_sync(0xffffffffu, y, d);
                if (lane >= d) y += t;
            }
            wsum[lane] = y;
        }
        __syncthreads();
        int woff = (wid == 0) ? 0 : wsum[wid-1];
        int excl = x - v + woff + s_carry;
        if (i < NN){ g_off[i] = excl; g_cur[i] = excl; }
        int btot = wsum[31];
        __syncthreads();
        if (tid == 0) s_carry += btot;
        __syncthreads();
    }
    if (tid == 0) g_off[NN] = s_carry;
}

__global__ void k_scatter(const int* __restrict__ ei, const float* __restrict__ ew){
    int e = blockIdx.x*blockDim.x + threadIdx.x;
    if (e < NE){
        int d = ei[NE + e];
        int p = atomicAdd(&g_cur[d], 1);
        g_csr[p] = make_float2(__int_as_float(ei[e]), ew[e]);
    }
}

// ---------------- aggregation: u = h + segment_sum(h[src]*w) ----------------
// one warp per node; lane covers 2 feature columns (float2)
__global__ void k_agg(){
    int node = blockIdx.x*8 + (threadIdx.x >> 5);
    int lane = threadIdx.x & 31;
    if (node >= NN) return;
    float2 acc = *(const float2*)&g_h[node*EMB + lane*2];
    int s = g_off[node], e = g_off[node+1];
    for (int p = s; p < e; p++){
        float2 m = g_csr[p];
        int src = __float_as_int(m.x);
        float w = m.y;
        float2 hv = *(const float2*)&g_h[src*EMB + lane*2];
        acc.x = fmaf(hv.x, w, acc.x);
        acc.y = fmaf(hv.y, w, acc.y);
    }
    *(float2*)&g_u[node*EMB + lane*2] = acc;
}

// ---------------- GEMM [NN x 64] @ [64 x 64] + bias ----------------
// MODE 0: encoder  Y=g_h,  X=param      (no stats)
// MODE 1: gemm1    Y=g_t1, X=g_u        (+ column stats)
// MODE 2: gemm2    Y=g_t2, X=bnrelu(g_t1) (+ column stats)
// block = 128 threads, 128 rows x 64 cols; thread tile 8x8 via f32x2
template<int MODE>
__global__ void __launch_bounds__(128, 2) k_gemm(const float* __restrict__ Xext,
                                                 const float* __restrict__ W,
                                                 const float* __restrict__ B){
    __shared__ float xs[EMB][128];   // [k][row] 32 KB
    __shared__ float ws[EMB][EMB];   // [k][col] 16 KB, reused as reduction buf
    int tid  = threadIdx.x;
    int row0 = blockIdx.x * 128;
    const float* X = (MODE == 0) ? Xext : (MODE == 1 ? g_u : g_t1);
    float*       Y = (MODE == 0) ? g_h  : (MODE == 1 ? g_t1 : g_t2);

    // load W -> shared (row-major, same layout)
    {
        const float4* w4 = (const float4*)W;
        float4* s4 = (float4*)ws;
        #pragma unroll
        for (int i = 0; i < 8; i++) s4[tid + i*128] = w4[tid + i*128];
    }
    // load X transposed into xs[k][row]  (+ fused BN-ReLU for MODE 2)
    {
        int grow = row0 + tid;
        #pragma unroll
        for (int k4 = 0; k4 < 16; k4++){
            float4 v = make_float4(0.f, 0.f, 0.f, 0.f);
            if (grow < NN) v = *(const float4*)&X[grow*EMB + k4*4];
            if (MODE == 2){
                float4 a = *(const float4*)&g_a[k4*4];
                float4 c = *(const float4*)&g_c[k4*4];
                v.x = fmaxf(fmaf(v.x, a.x, c.x), 0.f);
                v.y = fmaxf(fmaf(v.y, a.y, c.y), 0.f);
                v.z = fmaxf(fmaf(v.z, a.z, c.z), 0.f);
                v.w = fmaxf(fmaf(v.w, a.w, c.w), 0.f);
            }
            xs[k4*4+0][tid] = v.x; xs[k4*4+1][tid] = v.y;
            xs[k4*4+2][tid] = v.z; xs[k4*4+3][tid] = v.w;
        }
    }
    __syncthreads();

    int tc = tid & 7;     // 8 col-groups of 8 cols
    int tr = tid >> 3;    // 16 row-groups of 8 rows
    ull acc[8][4];
    #pragma unroll
    for (int i = 0; i < 8; i++)
        #pragma unroll
        for (int j = 0; j < 4; j++) acc[i][j] = 0ULL;

    #pragma unroll 4
    for (int k = 0; k < EMB; k++){
        float4 xlo = *(const float4*)&xs[k][tr*8];
        float4 xhi = *(const float4*)&xs[k][tr*8 + 4];
        float4 wlo = *(const float4*)&ws[k][tc*8];
        float4 whi = *(const float4*)&ws[k][tc*8 + 4];
        ull w01 = pack2(wlo.x, wlo.y), w23 = pack2(wlo.z, wlo.w);
        ull w45 = pack2(whi.x, whi.y), w67 = pack2(whi.z, whi.w);
        float xv[8] = {xlo.x, xlo.y, xlo.z, xlo.w, xhi.x, xhi.y, xhi.z, xhi.w};
        #pragma unroll
        for (int i = 0; i < 8; i++){
            ull xp = pack2(xv[i], xv[i]);
            ffma2(acc[i][0], xp, w01);
            ffma2(acc[i][1], xp, w23);
            ffma2(acc[i][2], xp, w45);
            ffma2(acc[i][3], xp, w67);
        }
    }
    __syncthreads();   // done with ws (k-loop reads), safe to reuse below

    float bias[8];
    {
        float4 blo = *(const float4*)&B[tc*8];
        float4 bhi = *(const float4*)&B[tc*8 + 4];
        bias[0]=blo.x; bias[1]=blo.y; bias[2]=blo.z; bias[3]=blo.w;
        bias[4]=bhi.x; bias[5]=bhi.y; bias[6]=bhi.z; bias[7]=bhi.w;
    }
    float bsum[8], bss[8];
    #pragma unroll
    for (int j = 0; j < 8; j++){ bsum[j] = 0.f; bss[j] = 0.f; }

    #pragma unroll
    for (int i = 0; i < 8; i++){
        int row = row0 + tr*8 + i;
        if (row < NN){
            float y[8];
            #pragma unroll
            for (int j = 0; j < 4; j++){
                float2 p = unpack2(acc[i][j]);
                y[2*j]   = p.x + bias[2*j];
                y[2*j+1] = p.y + bias[2*j+1];
            }
            *(float4*)&Y[row*EMB + tc*8]     = make_float4(y[0], y[1], y[2], y[3]);
            *(float4*)&Y[row*EMB + tc*8 + 4] = make_float4(y[4], y[5], y[6], y[7]);
            if (MODE >= 1){
                #pragma unroll
                for (int j = 0; j < 8; j++){
                    bsum[j] += y[j];
                    bss[j]  = fmaf(y[j], y[j], bss[j]);
                }
            }
        }
    }
    if (MODE >= 1){
        float* red  = &ws[0][0];
        float* red2 = red + 1024;
        #pragma unroll
        for (int j = 0; j < 8; j++){
            red [tr*64 + tc*8 + j] = bsum[j];
            red2[tr*64 + tc*8 + j] = bss[j];
        }
        __syncthreads();
        if (tid < 64){
            float s = 0.f;
            #pragma unroll
            for (int t = 0; t < 16; t++) s += red[t*64 + tid];
            atomicAdd(&g_sum[tid], s);
        } else {
            int c = tid - 64;
            float s = 0.f;
            #pragma unroll
            for (int t = 0; t < 16; t++) s += red2[t*64 + c];
            atomicAdd(&g_ss[c], s);
        }
    }
}

// ---------------- BN finalize: a = g*rstd, c = be - mean*a; zero stats ----------------
__global__ void k_fin(const float* __restrict__ g, const float* __restrict__ be){
    int c = threadIdx.x;                       // 64 threads
    float mean = g_sum[c] * (1.0f/NN);
    float var  = g_ss[c]  * (1.0f/NN) - mean*mean;
    float rstd = rsqrtf(var + BN_EPS);
    float a = g[c] * rstd;
    g_a[c] = a;
    g_c[c] = be[c] - mean*a;
    g_sum[c] = 0.f; g_ss[c] = 0.f;
}

// ---------------- residual: h = relu(bn(t2)) + h ----------------
__global__ void k_resid(float* __restrict__ outp){
    int i = blockIdx.x*blockDim.x + threadIdx.x;   // float4 index
    if (i < NN*16){
        int c4 = (i & 15) * 4;
        float4 a = *(const float4*)&g_a[c4];
        float4 c = *(const float4*)&g_c[c4];
        float4 t = ((const float4*)g_t2)[i];
        float4 h = ((const float4*)g_h)[i];
        float4 r;
        r.x = fmaxf(fmaf(t.x, a.x, c.x), 0.f) + h.x;
        r.y = fmaxf(fmaf(t.y, a.y, c.y), 0.f) + h.y;
        r.z = fmaxf(fmaf(t.z, a.z, c.z), 0.f) + h.z;
        r.w = fmaxf(fmaf(t.w, a.w, c.w), 0.f) + h.w;
        float4* dst = outp ? (float4*)outp : (float4*)g_h;
        dst[i] = r;
    }
}

// ---------------- driver ----------------
extern "C" void kernel_launch(void* const* d_in, const int* in_sizes, int n_in,
                              void* d_out, int out_size){
    const float* x   = (const float*)d_in[0];
    const int*   ei  = (const int*)  d_in[1];
    // d_in[2] = edge_attr (unused by reference)
    const float* ew  = (const float*)d_in[3];
    const float* aew = (const float*)d_in[4];
    const float* aeb = (const float*)d_in[5];
    const float* W1  = (const float*)d_in[6];
    const float* b1  = (const float*)d_in[7];
    const float* g1  = (const float*)d_in[8];
    const float* be1 = (const float*)d_in[9];
    const float* W2  = (const float*)d_in[10];
    const float* b2  = (const float*)d_in[11];
    const float* go  = (const float*)d_in[12];
    const float* beo = (const float*)d_in[13];
    float* out = (float*)d_out;

    k_init   <<<(NN + 255)/256, 256>>>();
    k_hist   <<<(NE + 255)/256, 256>>>(ei);
    k_scan   <<<1, 1024>>>();
    k_scatter<<<(NE + 255)/256, 256>>>(ei, ew);

    int gb = (NN + 127)/128;
    k_gemm<0><<<gb, 128>>>(x, aew, aeb);

    for (int l = 0; l < NL; l++){
        k_agg    <<<(NN + 7)/8, 256>>>();
        k_gemm<1><<<gb, 128>>>(nullptr, W1 + l*EMB*EMB, b1 + l*EMB);
        k_fin    <<<1, 64>>>(g1 + l*EMB, be1 + l*EMB);
        k_gemm<2><<<gb, 128>>>(nullptr, W2 + l*EMB*EMB, b2 + l*EMB);
        k_fin    <<<1, 64>>>(go + l*EMB, beo + l*EMB);
        k_resid  <<<(NN*16 + 255)/256, 256>>>(l == NL-1 ? out : nullptr);
    }
}